// round 9
// baseline (speedup 1.0000x reference)
#include <cuda_runtime.h>
#include <math.h>

// Problem shape
#define BDIM 8192          // batch rows (M)
#define IDIM 1024          // input features
#define ODIM 1024          // output features (N)
#define ND   9             // DEGREE+1
#define KDIM (IDIM * ND)   // 9216 GEMM-K

// -------- static device scratch (allocation-free per harness rules) --------
__device__ float g_W[KDIM * ODIM];   // [k=(i*9+d)][o]  ~37.7 MB
__device__ float g_t[IDIM * BDIM];   // transposed squashed input  [i][b]
__device__ float g_g[IDIM * BDIM];   // transposed gaussian        [i][b]

// -------- constants --------
__device__ __forceinline__ float hermA(int d) {
    // sqrt(2/d)
    const float a[9] = {0.f, 0.f, 1.0f, 0.8164965809f, 0.7071067812f,
                        0.6324555320f, 0.5773502692f, 0.5345224838f, 0.5f};
    return a[d];
}
__device__ __forceinline__ float hermB(int d) {
    // sqrt((d-1)/d)
    const float b[9] = {0.f, 0.f, 0.7071067812f, 0.8164965809f, 0.8660254038f,
                        0.8944271910f, 0.9128709292f, 0.9258200998f, 0.9354143467f};
    return b[d];
}

// ============================================================================
// Kernel 0: re-layout hermite_coeffs [I, O, D+1] -> g_W[(i*9+d)*O + o]
// ============================================================================
__global__ void prep_w_kernel(const float* __restrict__ c) {
    int idx = blockIdx.x * blockDim.x + threadIdx.x;
    if (idx >= KDIM * ODIM) return;
    int o = idx & (ODIM - 1);
    int k = idx >> 10;           // ODIM = 1024
    int i = k / ND;
    int d = k - i * ND;
    g_W[idx] = c[((size_t)i * ODIM + o) * ND + d];
}

// ============================================================================
// Kernel 1: t = tanh(x)*(sqrt(17)+1), g = exp(-t^2/2), stored TRANSPOSED [I,B]
// 32x32 smem transpose tile, block (32,8)
// ============================================================================
__global__ void prep_tg_kernel(const float* __restrict__ x) {
    __shared__ float ts[32][33];
    __shared__ float gs[32][33];
    const float S = 5.1231056256176605f;  // sqrt(17) + 1
    int i0 = blockIdx.x * 32;
    int b0 = blockIdx.y * 32;
    int txx = threadIdx.x;
    int tyy = threadIdx.y;
#pragma unroll
    for (int r = 0; r < 4; ++r) {
        int row = tyy + r * 8;            // within b-tile
        float v = x[(size_t)(b0 + row) * IDIM + i0 + txx];
        float t = tanhf(v) * S;
        ts[row][txx] = t;
        gs[row][txx] = expf(-0.5f * t * t);
    }
    __syncthreads();
#pragma unroll
    for (int r = 0; r < 4; ++r) {
        int row = tyy + r * 8;            // within i-tile
        size_t off = (size_t)(i0 + row) * BDIM + b0 + txx;
        g_t[off] = ts[txx][row];
        g_g[off] = gs[txx][row];
    }
}

// ============================================================================
// Kernel 2: fused GEMM  y[b,o] = sum_i sum_d H_d(t[b,i]) * W[(i,d), o]
// Block tile 128x128, 256 threads (16x16), 8x8 per thread.
// K loop = over input features i; each i = 9 rank-1 updates from smem slabs.
// Double-buffered smem, one __syncthreads per i.
// ============================================================================
__global__ __launch_bounds__(256)
void kan_gemm_kernel(float* __restrict__ y) {
    __shared__ float Hs[2][ND][128];
    __shared__ float Ws[2][ND][128];

    const int tid = threadIdx.x;
    const int tx = tid & 15;
    const int ty = tid >> 4;
    const int rowBase = blockIdx.y * 128;
    const int colBase = blockIdx.x * 128;
    const bool isH = (tid < 128);
    const int lj = isH ? tid : tid - 128;

    const float PIQ = 0.7511255444649425f;   // pi^(-1/4)
    const float SQ2 = 1.4142135623730951f;

    float acc[8][8];
#pragma unroll
    for (int a = 0; a < 8; ++a)
#pragma unroll
        for (int b = 0; b < 8; ++b) acc[a][b] = 0.0f;

    float sreg[ND];

    // stage loader: basis recurrence for 128 rows (threads 0..127),
    // 9 weight rows for 128 cols (threads 128..255)
    auto ldstage = [&](int i) {
        if (isH) {
            float t = g_t[(size_t)i * BDIM + rowBase + lj];
            float g = g_g[(size_t)i * BDIM + rowBase + lj];
            float h0 = PIQ * g;
            float h1 = SQ2 * t * h0;
            sreg[0] = h0;
            sreg[1] = h1;
#pragma unroll
            for (int d = 2; d < ND; ++d)
                sreg[d] = hermA(d) * t * sreg[d - 1] - hermB(d) * sreg[d - 2];
        } else {
            const float* wp = g_W + (size_t)i * (ND * ODIM) + colBase + lj;
#pragma unroll
            for (int d = 0; d < ND; ++d) sreg[d] = wp[(size_t)d * ODIM];
        }
    };

    ldstage(0);

    for (int i = 0; i < IDIM; ++i) {
        const int buf = i & 1;
        // commit staged regs to smem
        if (isH) {
#pragma unroll
            for (int d = 0; d < ND; ++d) Hs[buf][d][lj] = sreg[d];
        } else {
#pragma unroll
            for (int d = 0; d < ND; ++d) Ws[buf][d][lj] = sreg[d];
        }
        __syncthreads();
        if (i + 1 < IDIM) ldstage(i + 1);   // overlap next-stage loads with math

#pragma unroll
        for (int d = 0; d < ND; ++d) {
            float4 a0 = *(const float4*)&Hs[buf][d][ty * 8];
            float4 a1 = *(const float4*)&Hs[buf][d][ty * 8 + 4];
            float4 b0 = *(const float4*)&Ws[buf][d][tx * 8];
            float4 b1 = *(const float4*)&Ws[buf][d][tx * 8 + 4];
            float av[8] = {a0.x, a0.y, a0.z, a0.w, a1.x, a1.y, a1.z, a1.w};
            float bv[8] = {b0.x, b0.y, b0.z, b0.w, b1.x, b1.y, b1.z, b1.w};
#pragma unroll
            for (int ii = 0; ii < 8; ++ii)
#pragma unroll
                for (int jj = 0; jj < 8; ++jj)
                    acc[ii][jj] = fmaf(av[ii], bv[jj], acc[ii][jj]);
        }
    }

    // epilogue
#pragma unroll
    for (int ii = 0; ii < 8; ++ii) {
        int row = rowBase + ty * 8 + ii;
        float* yp = y + (size_t)row * ODIM + colBase + tx * 8;
        *(float4*)yp = make_float4(acc[ii][0], acc[ii][1], acc[ii][2], acc[ii][3]);
        *(float4*)(yp + 4) = make_float4(acc[ii][4], acc[ii][5], acc[ii][6], acc[ii][7]);
    }
}

// ============================================================================
extern "C" void kernel_launch(void* const* d_in, const int* in_sizes, int n_in,
                              void* d_out, int out_size) {
    const float* x = (const float*)d_in[0];
    const float* c = (const float*)d_in[1];
    // robustness: distinguish by element count (x: 8.39M, coeffs: 9.44M)
    if (n_in >= 2 && in_sizes[0] == KDIM * ODIM) {
        const float* tmp = x; x = c; c = tmp;
    }
    float* y = (float*)d_out;

    prep_w_kernel<<<(KDIM * ODIM + 255) / 256, 256>>>(c);
    prep_tg_kernel<<<dim3(IDIM / 32, BDIM / 32), dim3(32, 8)>>>(x);
    kan_gemm_kernel<<<dim3(ODIM / 128, BDIM / 128), 256>>>(y);
}

// round 11
// speedup vs baseline: 7.4252x; 7.4252x over previous
#include <cuda_runtime.h>
#include <cuda_fp16.h>
#include <math.h>
#include <stdint.h>

// ---------------- problem shape ----------------
#define BDIM 8192
#define IDIM 1024
#define ODIM 1024
#define ND   9
#define K9   (IDIM * ND)       // 9216

// ---------------- GEMM tiling ----------------
#define BM 128
#define BN 256
#define KB 64
#define NSTG 3
#define NKB (K9 / KB)          // 144
#define A_BYTES (BM * KB * 2)  // 16384
#define B_BYTES (KB * BN * 2)  // 32768
#define STG_BYTES (A_BYTES + B_BYTES)        // 49152
#define SMEM_BYTES (NSTG * STG_BYTES)        // 147456

// operand scaling (keeps fp16 operands in normal range)
#define SCALE_A 64.0f
#define SCALE_B 4096.0f
#define SCALE_OUT (1.0f / (SCALE_A * SCALE_B))

// ---------------- static device buffers ----------------
__device__ __half g_A[(size_t)BDIM * K9];   // [b][k], k = d*1024 + i, scaled x64
__device__ __half g_B[(size_t)K9 * ODIM];   // [k][o], scaled x4096

// ---------------- PTX helpers (sm_80-era: safe on compute_103) ----------------
__device__ __forceinline__ uint32_t smem_u32(const void* p) {
    uint32_t a;
    asm("{ .reg .u64 t; cvta.to.shared.u64 t, %1; cvt.u32.u64 %0, t; }" : "=r"(a) : "l"(p));
    return a;
}
__device__ __forceinline__ void cpasync16(uint32_t s, const void* g) {
    asm volatile("cp.async.cg.shared.global [%0], [%1], 16;"
                 :: "r"(s), "l"(__cvta_generic_to_global(g)));
}
__device__ __forceinline__ void ldsm4(uint32_t* r, uint32_t a) {
    asm volatile("ldmatrix.sync.aligned.m8n8.x4.shared.b16 {%0,%1,%2,%3}, [%4];"
                 : "=r"(r[0]), "=r"(r[1]), "=r"(r[2]), "=r"(r[3]) : "r"(a));
}
__device__ __forceinline__ void ldsm4t(uint32_t* r, uint32_t a) {
    asm volatile("ldmatrix.sync.aligned.m8n8.x4.trans.shared.b16 {%0,%1,%2,%3}, [%4];"
                 : "=r"(r[0]), "=r"(r[1]), "=r"(r[2]), "=r"(r[3]) : "r"(a));
}
__device__ __forceinline__ void mma16816(float* d, const uint32_t* a, const uint32_t* b) {
    asm volatile(
        "mma.sync.aligned.m16n8k16.row.col.f32.f16.f16.f32 "
        "{%0,%1,%2,%3}, {%4,%5,%6,%7}, {%8,%9}, {%0,%1,%2,%3};"
        : "+f"(d[0]), "+f"(d[1]), "+f"(d[2]), "+f"(d[3])
        : "r"(a[0]), "r"(a[1]), "r"(a[2]), "r"(a[3]), "r"(b[0]), "r"(b[1]));
}

// smem swizzles (XOR row&7 into 16B-segment index)
__device__ __forceinline__ uint32_t swzA(uint32_t off) { return off ^ ((off >> 3) & 0x70); } // 128B rows
__device__ __forceinline__ uint32_t swzB(uint32_t off) { return off ^ ((off >> 5) & 0x70); } // 512B rows

// ---------------- prep kernels ----------------
__global__ void prep_basis_kernel(const float* __restrict__ x) {
    int idx = blockIdx.x * blockDim.x + threadIdx.x;
    int b = idx >> 10;
    int i = idx & 1023;
    const float S = 5.1231056256176605f;    // sqrt(17)+1
    const float PIQ = 0.7511255444649425f;  // pi^-1/4
    const float SQ2 = 1.4142135623730951f;
    const float ha[9] = {0.f, 0.f, 1.0f, 0.8164965809f, 0.7071067812f,
                         0.6324555320f, 0.5773502692f, 0.5345224838f, 0.5f};
    const float hb[9] = {0.f, 0.f, 0.7071067812f, 0.8164965809f, 0.8660254038f,
                         0.8944271910f, 0.9128709292f, 0.9258200998f, 0.9354143467f};
    float t = tanhf(x[idx]) * S;
    float g = expf(-0.5f * t * t);
    float h[ND];
    h[0] = PIQ * g;
    h[1] = SQ2 * t * h[0];
#pragma unroll
    for (int d = 2; d < ND; ++d) h[d] = ha[d] * t * h[d - 1] - hb[d] * h[d - 2];
    size_t base = (size_t)b * K9 + i;
#pragma unroll
    for (int d = 0; d < ND; ++d)
        g_A[base + (size_t)d * 1024] = __float2half_rn(h[d] * SCALE_A);
}

__global__ void prep_w_kernel(const float* __restrict__ c) {
    int idx = blockIdx.x * blockDim.x + threadIdx.x;   // idx = k*1024 + o
    if (idx >= K9 * ODIM) return;
    int o = idx & 1023;
    int k = idx >> 10;
    int i = k & 1023;
    int d = k >> 10;
    float w = c[((size_t)i * ODIM + o) * ND + d];
    g_B[idx] = __float2half_rn(w * SCALE_B);
}

// ---------------- HMMA GEMM: y[8192,1024] = A[8192,9216] * B[9216,1024] ----------------
__global__ __launch_bounds__(512, 1)
void kan_hmma_kernel(float* __restrict__ y) {
    extern __shared__ __align__(1024) char smem[];
    const uint32_t sb = smem_u32(smem);
    const int tid = threadIdx.x;
    const int wid = tid >> 5;
    const int lane = tid & 31;
    const int wm = wid & 3;         // 4 warp-rows of 32
    const int wn = wid >> 2;        // 4 warp-cols of 64
    const int rowBase = blockIdx.y * BM;
    const int colBase = blockIdx.x * BN;
    const __half* gA = g_A;
    const __half* gB = g_B;

    float acc[2][8][4];
#pragma unroll
    for (int a = 0; a < 2; ++a)
#pragma unroll
        for (int b = 0; b < 8; ++b)
#pragma unroll
            for (int q = 0; q < 4; ++q) acc[a][b][q] = 0.0f;

    auto load_stage = [&](int kb, int stg) {
        uint32_t sA = sb + stg * STG_BYTES;
        uint32_t sBs = sA + A_BYTES;
        // A tile 128x64 fp16 (128B rows): 1024 x 16B segments
#pragma unroll
        for (int it = 0; it < 2; ++it) {
            int s = tid + it * 512;
            int row = s >> 3, c = s & 7;
            const __half* gp = gA + (size_t)(rowBase + row) * K9 + kb * KB + c * 8;
            cpasync16(sA + swzA(row * 128 + c * 16), gp);
        }
        // B tile 64x256 fp16 (512B rows): 2048 x 16B segments
#pragma unroll
        for (int it = 0; it < 4; ++it) {
            int s = tid + it * 512;
            int row = s >> 5, c = s & 31;
            const __half* gp = gB + (size_t)(kb * KB + row) * ODIM + colBase + c * 8;
            cpasync16(sBs + swzB(row * 512 + c * 16), gp);
        }
        asm volatile("cp.async.commit_group;");
    };

    // prologue: stages 0,1
    load_stage(0, 0);
    load_stage(1, 1);
    asm volatile("cp.async.wait_group 1;");
    __syncthreads();

    for (int kb = 0; kb < NKB; ++kb) {
        if (kb + 2 < NKB) load_stage(kb + 2, (kb + 2) % NSTG);

        const int stg = kb % NSTG;
        const uint32_t sA = sb + stg * STG_BYTES;
        const uint32_t sBs = sA + A_BYTES;

#pragma unroll
        for (int ks = 0; ks < 4; ++ks) {          // 4 x k16
            uint32_t aF[2][4];
#pragma unroll
            for (int mt = 0; mt < 2; ++mt) {
                int row = wm * 32 + mt * 16 + (lane & 15);
                uint32_t off = row * 128 + ks * 32 + (lane >> 4) * 16;
                ldsm4(aF[mt], sA + swzA(off));
            }
            uint32_t bF[4][4];
#pragma unroll
            for (int nt = 0; nt < 4; ++nt) {      // n16 tiles
                int krow = ks * 16 + (lane & 15);
                uint32_t off = krow * 512 + (wn * 64 + nt * 16) * 2 + (lane >> 4) * 16;
                ldsm4t(bF[nt], sBs + swzB(off));
            }
#pragma unroll
            for (int mt = 0; mt < 2; ++mt)
#pragma unroll
                for (int nt = 0; nt < 4; ++nt) {
                    mma16816(acc[mt][nt * 2],     aF[mt], &bF[nt][0]);
                    mma16816(acc[mt][nt * 2 + 1], aF[mt], &bF[nt][2]);
                }
        }

        if (kb + 2 < NKB) asm volatile("cp.async.wait_group 1;");
        else              asm volatile("cp.async.wait_group 0;");
        __syncthreads();
    }

    // epilogue: scale back and store
    const float SC = SCALE_OUT;
#pragma unroll
    for (int mt = 0; mt < 2; ++mt) {
#pragma unroll
        for (int n8 = 0; n8 < 8; ++n8) {
            int r0 = rowBase + wm * 32 + mt * 16 + (lane >> 2);
            int c0 = colBase + wn * 64 + n8 * 8 + (lane & 3) * 2;
            float2 v0 = make_float2(acc[mt][n8][0] * SC, acc[mt][n8][1] * SC);
            float2 v1 = make_float2(acc[mt][n8][2] * SC, acc[mt][n8][3] * SC);
            *(float2*)&y[(size_t)r0 * ODIM + c0] = v0;
            *(float2*)&y[(size_t)(r0 + 8) * ODIM + c0] = v1;
        }
    }
}

// ---------------- host ----------------
extern "C" void kernel_launch(void* const* d_in, const int* in_sizes, int n_in,
                              void* d_out, int out_size) {
    const float* x = (const float*)d_in[0];
    const float* c = (const float*)d_in[1];
    if (n_in >= 2 && in_sizes[0] == K9 * ODIM) {   // coeffs first? swap
        const float* t = x; x = c; c = t;
    }
    float* y = (float*)d_out;

    prep_w_kernel<<<(K9 * ODIM + 255) / 256, 256>>>(c);
    prep_basis_kernel<<<(BDIM * IDIM) / 256, 256>>>(x);

    static bool attr_set = false;
    cudaFuncSetAttribute(kan_hmma_kernel,
                         cudaFuncAttributeMaxDynamicSharedMemorySize, SMEM_BYTES);
    (void)attr_set;

    kan_hmma_kernel<<<dim3(ODIM / BN, BDIM / BM), 512, SMEM_BYTES>>>(y);
}